// round 5
// baseline (speedup 1.0000x reference)
#include <cuda_runtime.h>
#include <cstdint>

#define SEQ 2048
#define HID 4096
#define NH  32
#define NKV 8
#define HD  128
#define ROPE_D 64

// Scratch (device globals -> no allocations)
__device__ float g_q [(size_t)SEQ * NH  * HD];   // 32 MB
__device__ float g_k [(size_t)SEQ * NKV * HD];   // 8 MB
__device__ float g_v [(size_t)SEQ * NKV * HD];   // 8 MB
__device__ float g_sc[(size_t)NH * SEQ * SEQ];   // 512 MB
__device__ float g_at[(size_t)SEQ * NH  * HD];   // 32 MB
// tf32-rounded copies of the read-only inputs
__device__ float g_X [(size_t)SEQ * HID];        // 32 MB
__device__ float g_Wq[(size_t)HID * NH  * HD];   // 64 MB
__device__ float g_Wk[(size_t)HID * NKV * HD];   // 16 MB
__device__ float g_Wv[(size_t)HID * NKV * HD];   // 16 MB
__device__ float g_Wo[(size_t)NH * HD * HID];    // 64 MB

// ---------------------------------------------------------------------------
// helpers
// ---------------------------------------------------------------------------
__device__ __forceinline__ uint32_t smem_u32(const void* p) {
    return (uint32_t)__cvta_generic_to_shared(p);
}
__device__ __forceinline__ void cp16(uint32_t s, const void* g) {
    asm volatile("cp.async.cg.shared.global [%0], [%1], 16;\n" :: "r"(s), "l"(g));
}
__device__ __forceinline__ float rnd_tf32(float x) {
    uint32_t u;
    asm("cvt.rna.tf32.f32 %0, %1;" : "=r"(u) : "f"(x));
    return __uint_as_float(u);
}

__global__ void round_copy(const float* __restrict__ src, float* __restrict__ dst, int n) {
    for (int i = blockIdx.x * blockDim.x + threadIdx.x; i < n; i += gridDim.x * blockDim.x)
        dst[i] = rnd_tf32(src[i]);
}

// ---------------------------------------------------------------------------
// tf32 tensor-core GEMM: C[M,N] = alpha * A[M,K] * op(B)
//   TRANSB=1: B is [N,K] row-major (B^T applied). TRANSB=0: B is [K,N].
// Tiles: 128x128x32, 8 warps (2m x 4n), warp tile 64x32, mma m16n8k8 tf32.
// 3-stage cp.async pipeline. All inputs must already be tf32-rounded values.
// CAUSAL&&TRANSB: skip tiles with bn>bm. CAUSAL&&!TRANSB: K limited to (bm+1)*128.
// ---------------------------------------------------------------------------
#define STAGEF 8448            // floats per stage: A 128*32 + B 32*136 (padded)
#define SMEM_BYTES (3 * STAGEF * 4)

template<int TRANSB, int CAUSAL, int ROUND_OUT>
__global__ __launch_bounds__(256)
void mma_gemm(const float* __restrict__ A, const float* __restrict__ B,
              float* __restrict__ C, int M, int N, int K,
              int lda, int ldb, int ldc,
              long long sA, long long sB, long long sC, int zdivB,
              float alpha)
{
    int bm = blockIdx.y, bn = blockIdx.x, bz = blockIdx.z;
    if (CAUSAL && TRANSB && bn > bm) return;

    A += (long long)bz * sA;
    B += (long long)(bz / zdivB) * sB;
    C += (long long)bz * sC;

    int Kend = K;
    if (CAUSAL && !TRANSB) {
        int lim = (bm + 1) * 128;
        Kend = (K < lim) ? K : lim;
    }
    int niter = Kend >> 5;

    extern __shared__ float smem[];
    int tid = threadIdx.x;
    int lane = tid & 31, warp = tid >> 5;
    int wm = warp & 1, wn = warp >> 1;

    const float* Ag = A + (size_t)(bm * 128) * lda;
    const float* Bg1 = B + (size_t)(bn * 128) * ldb;   // TRANSB=1 base
    const float* Bg0 = B + bn * 128;                   // TRANSB=0 base

    auto issue_tiles = [&](int stage, int k0) {
        float* As = smem + stage * STAGEF;
        float* Bs = As + 4096;
#pragma unroll
        for (int i = 0; i < 4; i++) {
            int ch = tid + i * 256;
            int r = ch >> 3, c = ch & 7;
            cp16(smem_u32(As + r * 32 + ((c ^ (r & 7)) << 2)),
                 Ag + (size_t)r * lda + k0 + c * 4);
        }
        if (TRANSB) {
#pragma unroll
            for (int i = 0; i < 4; i++) {
                int ch = tid + i * 256;
                int r = ch >> 3, c = ch & 7;
                cp16(smem_u32(Bs + r * 32 + ((c ^ (r & 7)) << 2)),
                     Bg1 + (size_t)r * ldb + k0 + c * 4);
            }
        } else {
#pragma unroll
            for (int i = 0; i < 4; i++) {
                int ch = tid + i * 256;
                int r = ch >> 5, c = ch & 31;
                cp16(smem_u32(Bs + r * 136 + c * 4),
                     Bg0 + (size_t)(k0 + r) * ldb + c * 4);
            }
        }
    };

    float acc[4][4][4];
#pragma unroll
    for (int i = 0; i < 4; i++)
#pragma unroll
        for (int j = 0; j < 4; j++)
#pragma unroll
            for (int t = 0; t < 4; t++) acc[i][j][t] = 0.f;

    // pipeline prologue: stages 0,1
    issue_tiles(0, 0);
    asm volatile("cp.async.commit_group;");
    if (niter > 1) issue_tiles(1, 32);
    asm volatile("cp.async.commit_group;");
    asm volatile("cp.async.wait_group 1;");
    __syncthreads();

    for (int it = 0; it < niter; it++) {
        int cur = it % 3;
        int nxt = it + 2;
        if (nxt < niter) issue_tiles(nxt % 3, nxt * 32);
        asm volatile("cp.async.commit_group;");

        const float* As = smem + cur * STAGEF;
        const float* Bsm = As + 4096;
#pragma unroll
        for (int kk = 0; kk < 4; kk++) {
            uint32_t a[4][4];
#pragma unroll
            for (int im = 0; im < 4; im++) {
                int r = wm * 64 + im * 16 + ((lane >> 3) & 1) * 8 + (lane & 7);
                int c = kk * 2 + (lane >> 4);
                uint32_t addr = smem_u32(As + r * 32 + ((c ^ (r & 7)) << 2));
                asm volatile("ldmatrix.sync.aligned.m8n8.x4.shared.b16 {%0,%1,%2,%3}, [%4];"
                             : "=r"(a[im][0]), "=r"(a[im][1]), "=r"(a[im][2]), "=r"(a[im][3])
                             : "r"(addr));
            }
            uint32_t b[4][2];
            if (TRANSB) {
#pragma unroll
                for (int jp = 0; jp < 2; jp++) {
                    int n = wn * 32 + jp * 16 + (lane >> 4) * 8 + (lane & 7);
                    int c = kk * 2 + ((lane >> 3) & 1);
                    uint32_t addr = smem_u32(Bsm + n * 32 + ((c ^ (n & 7)) << 2));
                    asm volatile("ldmatrix.sync.aligned.m8n8.x4.shared.b16 {%0,%1,%2,%3}, [%4];"
                                 : "=r"(b[2 * jp][0]), "=r"(b[2 * jp][1]),
                                   "=r"(b[2 * jp + 1][0]), "=r"(b[2 * jp + 1][1])
                                 : "r"(addr));
                }
            } else {
                int gid = lane >> 2, tig = lane & 3;
#pragma unroll
                for (int jn = 0; jn < 4; jn++) {
                    int n0 = wn * 32 + jn * 8 + gid;
                    b[jn][0] = __float_as_uint(Bsm[(kk * 8 + tig) * 136 + n0]);
                    b[jn][1] = __float_as_uint(Bsm[(kk * 8 + tig + 4) * 136 + n0]);
                }
            }
#pragma unroll
            for (int im = 0; im < 4; im++)
#pragma unroll
                for (int jn = 0; jn < 4; jn++) {
                    asm volatile(
                        "mma.sync.aligned.m16n8k8.row.col.f32.tf32.tf32.f32 "
                        "{%0,%1,%2,%3}, {%4,%5,%6,%7}, {%8,%9}, {%0,%1,%2,%3};"
                        : "+f"(acc[im][jn][0]), "+f"(acc[im][jn][1]),
                          "+f"(acc[im][jn][2]), "+f"(acc[im][jn][3])
                        : "r"(a[im][0]), "r"(a[im][1]), "r"(a[im][2]), "r"(a[im][3]),
                          "r"(b[jn][0]), "r"(b[jn][1]));
                }
        }
        asm volatile("cp.async.wait_group 1;");
        __syncthreads();
    }

    // epilogue
    int gid = lane >> 2, tig = lane & 3;
#pragma unroll
    for (int im = 0; im < 4; im++) {
        int row0 = bm * 128 + wm * 64 + im * 16 + gid;
#pragma unroll
        for (int jn = 0; jn < 4; jn++) {
            int col = bn * 128 + wn * 32 + jn * 8 + tig * 2;
            float v0 = alpha * acc[im][jn][0];
            float v1 = alpha * acc[im][jn][1];
            float v2 = alpha * acc[im][jn][2];
            float v3 = alpha * acc[im][jn][3];
            if (ROUND_OUT) {
                v0 = rnd_tf32(v0); v1 = rnd_tf32(v1);
                v2 = rnd_tf32(v2); v3 = rnd_tf32(v3);
            }
            *(float2*)&C[(size_t)row0 * ldc + col] = make_float2(v0, v1);
            *(float2*)&C[(size_t)(row0 + 8) * ldc + col] = make_float2(v2, v3);
        }
    }
}

// ---------------------------------------------------------------------------
// RoPE on Q (32 heads) and K (8 heads), first 64 dims. Outputs tf32-rounded.
// ---------------------------------------------------------------------------
__global__ void rope_kernel(float* __restrict__ q, float* __restrict__ k,
                            const float* __restrict__ cosb,
                            const float* __restrict__ sinb)
{
    int idx = blockIdx.x * blockDim.x + threadIdx.x;
    const int total = SEQ * (NH + NKV) * (ROPE_D / 2);
    if (idx >= total) return;
    int p = idx & 31;
    int rest = idx >> 5;
    int head = rest % (NH + NKV);
    int s = rest / (NH + NKV);

    float* x;
    if (head < NH) x = q + (size_t)s * (NH * HD) + head * HD;
    else           x = k + (size_t)s * (NKV * HD) + (head - NH) * HD;

    float x0 = x[p], x1 = x[p + 32];
    const float* cp = cosb + (size_t)s * ROPE_D;
    const float* sp = sinb + (size_t)s * ROPE_D;
    float c0 = cp[p], s0 = sp[p];
    float c1 = cp[p + 32], s1 = sp[p + 32];
    x[p]      = rnd_tf32(x0 * c0 - x1 * s0);
    x[p + 32] = rnd_tf32(x1 * c1 + x0 * s1);
}

// ---------------------------------------------------------------------------
// Row softmax with causal mask + sink logit. P written tf32-rounded.
// ---------------------------------------------------------------------------
__global__ void softmax_kernel(float* __restrict__ sc,
                               const float* __restrict__ sinks)
{
    int q = blockIdx.x, h = blockIdx.y;
    float* row = sc + ((size_t)h * SEQ + q) * SEQ;
    int len = q + 1;
    int tid = threadIdx.x;
    __shared__ float red[256];

    float m = -1e30f;
    for (int i = tid; i < len; i += 256) m = fmaxf(m, row[i]);
    red[tid] = m;
    __syncthreads();
    for (int s2 = 128; s2 > 0; s2 >>= 1) {
        if (tid < s2) red[tid] = fmaxf(red[tid], red[tid + s2]);
        __syncthreads();
    }
    float sink = sinks[h];
    m = fmaxf(red[0], sink);
    __syncthreads();

    float sum = 0.f;
    for (int i = tid; i < len; i += 256) {
        float e = expf(row[i] - m);
        row[i] = e;
        sum += e;
    }
    red[tid] = sum;
    __syncthreads();
    for (int s2 = 128; s2 > 0; s2 >>= 1) {
        if (tid < s2) red[tid] += red[tid + s2];
        __syncthreads();
    }
    float inv = 1.f / (red[0] + expf(sink - m));

    for (int i = tid; i < len; i += 256) row[i] = rnd_tf32(row[i] * inv);
    for (int i = len + tid; i < SEQ; i += 256) row[i] = 0.f;
}

// ---------------------------------------------------------------------------
extern "C" void kernel_launch(void* const* d_in, const int* in_sizes, int n_in,
                              void* d_out, int out_size)
{
    const float* X_in  = (const float*)d_in[0];
    const float* cosb  = (const float*)d_in[1];
    const float* sinb  = (const float*)d_in[2];
    const float* Wq_in = (const float*)d_in[4];
    const float* Wk_in = (const float*)d_in[5];
    const float* Wv_in = (const float*)d_in[6];
    const float* Wo_in = (const float*)d_in[7];
    const float* sinks = (const float*)d_in[8];
    float* out = (float*)d_out;

    float *q, *k, *v, *sc, *at, *X, *Wq, *Wk, *Wv, *Wo;
    cudaGetSymbolAddress((void**)&q,  g_q);
    cudaGetSymbolAddress((void**)&k,  g_k);
    cudaGetSymbolAddress((void**)&v,  g_v);
    cudaGetSymbolAddress((void**)&sc, g_sc);
    cudaGetSymbolAddress((void**)&at, g_at);
    cudaGetSymbolAddress((void**)&X,  g_X);
    cudaGetSymbolAddress((void**)&Wq, g_Wq);
    cudaGetSymbolAddress((void**)&Wk, g_Wk);
    cudaGetSymbolAddress((void**)&Wv, g_Wv);
    cudaGetSymbolAddress((void**)&Wo, g_Wo);

    cudaFuncSetAttribute((const void*)mma_gemm<0,0,1>, cudaFuncAttributeMaxDynamicSharedMemorySize, SMEM_BYTES);
    cudaFuncSetAttribute((const void*)mma_gemm<0,0,0>, cudaFuncAttributeMaxDynamicSharedMemorySize, SMEM_BYTES);
    cudaFuncSetAttribute((const void*)mma_gemm<1,1,0>, cudaFuncAttributeMaxDynamicSharedMemorySize, SMEM_BYTES);
    cudaFuncSetAttribute((const void*)mma_gemm<0,1,1>, cudaFuncAttributeMaxDynamicSharedMemorySize, SMEM_BYTES);

    const float scale = 0.08838834764831845f;  // 128^-0.5

    // 0. tf32-round the read-only inputs (rne; avoids biased HW truncation)
    round_copy<<<4096, 256>>>(X_in,  X,  SEQ * HID);
    round_copy<<<8192, 256>>>(Wq_in, Wq, HID * NH * HD);
    round_copy<<<4096, 256>>>(Wk_in, Wk, HID * NKV * HD);
    round_copy<<<4096, 256>>>(Wv_in, Wv, HID * NKV * HD);
    round_copy<<<8192, 256>>>(Wo_in, Wo, NH * HD * HID);

    // 1-3. QKV projections (outputs rounded)
    mma_gemm<0,0,1><<<dim3(NH*HD/128, SEQ/128, 1), 256, SMEM_BYTES>>>(
        X, Wq, q, SEQ, NH*HD, HID, HID, NH*HD, NH*HD, 0, 0, 0, 1, 1.f);
    mma_gemm<0,0,1><<<dim3(NKV*HD/128, SEQ/128, 1), 256, SMEM_BYTES>>>(
        X, Wk, k, SEQ, NKV*HD, HID, HID, NKV*HD, NKV*HD, 0, 0, 0, 1, 1.f);
    mma_gemm<0,0,1><<<dim3(NKV*HD/128, SEQ/128, 1), 256, SMEM_BYTES>>>(
        X, Wv, v, SEQ, NKV*HD, HID, HID, NKV*HD, NKV*HD, 0, 0, 0, 1, 1.f);

    // 4. RoPE (in place; rounded)
    {
        int total = SEQ * (NH + NKV) * (ROPE_D / 2);
        rope_kernel<<<(total + 255) / 256, 256>>>(q, k, cosb, sinb);
    }

    // 5. scores = scale * Q @ K^T (causal tile skip)
    mma_gemm<1,1,0><<<dim3(SEQ/128, SEQ/128, NH), 256, SMEM_BYTES>>>(
        q, k, sc, SEQ, SEQ, HD,
        NH*HD, NKV*HD, SEQ,
        (long long)HD, (long long)HD, (long long)SEQ * SEQ, NH / NKV,
        scale);

    // 6. causal softmax with sink (P rounded)
    softmax_kernel<<<dim3(SEQ, NH), 256>>>(sc, sinks);

    // 7. attn = P @ V (K-limited by causal; rounded)
    mma_gemm<0,1,1><<<dim3(HD/128, SEQ/128, NH), 256, SMEM_BYTES>>>(
        sc, v, at, SEQ, HD, SEQ,
        SEQ, NKV*HD, NH*HD,
        (long long)SEQ * SEQ, (long long)HD, (long long)HD, NH / NKV,
        1.f);

    // 8. output projection (fp32 out)
    mma_gemm<0,0,0><<<dim3(HID/128, SEQ/128, 1), 256, SMEM_BYTES>>>(
        at, Wo, out, SEQ, HID, NH*HD, NH*HD, HID, HID, 0, 0, 0, 1, 1.f);
}

// round 6
// speedup vs baseline: 1.2646x; 1.2646x over previous
#include <cuda_runtime.h>
#include <cuda_fp16.h>
#include <cstdint>

#define SEQ 2048
#define HID 4096
#define NH  32
#define NKV 8
#define HD  128
#define SCALE 0.08838834764831845f

// ---------------- scratch (device globals; no allocations) ----------------
__device__ __half g_Xh  [(size_t)SEQ * HID];
__device__ __half g_Xl  [(size_t)SEQ * HID];
__device__ __half g_Wqkv[(size_t)HID * 6144];   // [Wq | Wk | Wv] fp16
__device__ __half g_Woh [(size_t)4096 * HID];
__device__ float  g_qkvf[(size_t)SEQ * 6144];   // fused QKV output fp32
__device__ __half g_qh  [(size_t)SEQ * 4096];
__device__ __half g_ql  [(size_t)SEQ * 4096];
__device__ __half g_kh  [(size_t)SEQ * 1024];
__device__ __half g_vh  [(size_t)SEQ * 1024];
__device__ __half g_vl  [(size_t)SEQ * 1024];
__device__ __half g_ath [(size_t)SEQ * 4096];
__device__ __half g_atl [(size_t)SEQ * 4096];

// ---------------- helpers ----------------
__device__ __forceinline__ uint32_t smem_u32(const void* p) {
    return (uint32_t)__cvta_generic_to_shared(p);
}
__device__ __forceinline__ void cp16(uint32_t s, const void* g) {
    asm volatile("cp.async.cg.shared.global [%0], [%1], 16;\n" :: "r"(s), "l"(g));
}
#define CP_COMMIT() asm volatile("cp.async.commit_group;")
#define CP_WAIT(n)  asm volatile("cp.async.wait_group %0;" :: "n"(n))

__device__ __forceinline__ void ldsm4(uint32_t* r, uint32_t a) {
    asm volatile("ldmatrix.sync.aligned.m8n8.x4.shared.b16 {%0,%1,%2,%3}, [%4];"
                 : "=r"(r[0]), "=r"(r[1]), "=r"(r[2]), "=r"(r[3]) : "r"(a));
}
__device__ __forceinline__ void ldsm4t(uint32_t* r, uint32_t a) {
    asm volatile("ldmatrix.sync.aligned.m8n8.x4.trans.shared.b16 {%0,%1,%2,%3}, [%4];"
                 : "=r"(r[0]), "=r"(r[1]), "=r"(r[2]), "=r"(r[3]) : "r"(a));
}
__device__ __forceinline__ void mma_f16(float* c, const uint32_t* a, const uint32_t* b) {
    asm volatile("mma.sync.aligned.m16n8k16.row.col.f32.f16.f16.f32 "
                 "{%0,%1,%2,%3},{%4,%5,%6,%7},{%8,%9},{%0,%1,%2,%3};"
                 : "+f"(c[0]), "+f"(c[1]), "+f"(c[2]), "+f"(c[3])
                 : "r"(a[0]), "r"(a[1]), "r"(a[2]), "r"(a[3]), "r"(b[0]), "r"(b[1]));
}
__device__ __forceinline__ uint32_t pack_h2(float a, float b) {
    __half2 t = __floats2half2_rn(a, b);
    return *reinterpret_cast<uint32_t*>(&t);
}

// ---------------- split kernels ----------------
__global__ void split2_kernel(const float* __restrict__ s, __half* __restrict__ h,
                              __half* __restrict__ l, int n) {
    for (int i = blockIdx.x * blockDim.x + threadIdx.x; i < n; i += gridDim.x * blockDim.x) {
        float x = s[i];
        __half hh = __float2half_rn(x);
        h[i] = hh;
        l[i] = __float2half_rn(x - __half2float(hh));
    }
}
// strided hi-only split: dst[r*ldd + col0 + c] = fp16(src[r*cols + c])
__global__ void split1s_kernel(const float* __restrict__ s, __half* __restrict__ d,
                               int rows, int cols, int ldd, int col0) {
    int n = rows * cols;
    for (int i = blockIdx.x * blockDim.x + threadIdx.x; i < n; i += gridDim.x * blockDim.x) {
        int r = i / cols, c = i - r * cols;
        d[(size_t)r * ldd + col0 + c] = __float2half_rn(s[i]);
    }
}
// v slice (cols 5120..6143 of qkvf) -> hi+lo
__global__ void vsplit_kernel(const float* __restrict__ qkvf, __half* __restrict__ vh,
                              __half* __restrict__ vl) {
    int n = SEQ * 1024;
    for (int i = blockIdx.x * blockDim.x + threadIdx.x; i < n; i += gridDim.x * blockDim.x) {
        int r = i >> 10, c = i & 1023;
        float x = qkvf[(size_t)r * 6144 + 5120 + c];
        __half hh = __float2half_rn(x);
        vh[i] = hh;
        vl[i] = __float2half_rn(x - __half2float(hh));
    }
}

// ---------------------------------------------------------------------------
// fp16 x2 GEMM: C[M,N] (fp32) = (Ah + Al) * B
// A row-major [M,K] (hi,lo fp16), B row-major [K,N] fp16.
// CTA 128x128 k-step 32, 4 warps (2x2) each 64x64, 3-stage cp.async.
// smem/stage: A hi 128x40 + A lo 128x40 + B 32x136 halves.
// ---------------------------------------------------------------------------
#define PSTG 14592
#define PSMEM (3 * PSTG * 2)

__global__ __launch_bounds__(128, 2)
void hgemm(const __half* __restrict__ Ah, const __half* __restrict__ Al,
           const __half* __restrict__ B, float* __restrict__ C,
           int M, int N, int K, int lda, int ldb, int ldc)
{
    extern __shared__ __half sm[];
    const int bm = blockIdx.y, bn = blockIdx.x;
    const int tid = threadIdx.x, lane = tid & 31, warp = tid >> 5;
    const int wm = warp & 1, wn = warp >> 1;

    const __half* Agh = Ah + (size_t)bm * 128 * lda;
    const __half* Agl = Al + (size_t)bm * 128 * lda;
    const __half* Bg  = B + bn * 128;

    auto load_stage = [&](int st, int k0) {
        __half* sa = sm + st * PSTG;
        __half* sl = sa + 5120;
        __half* sb = sl + 5120;
#pragma unroll
        for (int i = 0; i < 4; i++) {
            int id = tid + i * 128;
            int r = id >> 2, u = id & 3;
            cp16(smem_u32(sa + r * 40 + u * 8), Agh + (size_t)r * lda + k0 + u * 8);
            cp16(smem_u32(sl + r * 40 + u * 8), Agl + (size_t)r * lda + k0 + u * 8);
        }
#pragma unroll
        for (int i = 0; i < 4; i++) {
            int id = tid + i * 128;
            int r = id >> 4, u = id & 15;
            cp16(smem_u32(sb + r * 136 + u * 8), Bg + (size_t)(k0 + r) * ldb + u * 8);
        }
    };

    float acc[4][8][4];
#pragma unroll
    for (int a = 0; a < 4; a++)
#pragma unroll
        for (int b = 0; b < 8; b++)
#pragma unroll
            for (int c = 0; c < 4; c++) acc[a][b][c] = 0.f;

    const int nk = K >> 5;
    load_stage(0, 0);  CP_COMMIT();
    load_stage(1, 32); CP_COMMIT();
    CP_WAIT(1);
    __syncthreads();

    for (int it = 0; it < nk; it++) {
        int cur = it % 3;
        int nx = it + 2;
        if (nx < nk) load_stage(nx % 3, nx * 32);
        CP_COMMIT();

        const __half* sa = sm + cur * PSTG;
        const __half* sl = sa + 5120;
        const __half* sb = sl + 5120;
#pragma unroll
        for (int kk = 0; kk < 2; kk++) {
            uint32_t ah[4][4], al[4][4], bb[8][2];
#pragma unroll
            for (int im = 0; im < 4; im++) {
                int r = wm * 64 + im * 16 + (lane & 15);
                int u = kk * 2 + (lane >> 4);
                ldsm4(ah[im], smem_u32(sa + r * 40 + u * 8));
                ldsm4(al[im], smem_u32(sl + r * 40 + u * 8));
            }
#pragma unroll
            for (int jp = 0; jp < 4; jp++) {
                int r = kk * 16 + (lane & 15);
                int u = wn * 8 + jp * 2 + (lane >> 4);
                uint32_t t[4];
                ldsm4t(t, smem_u32(sb + r * 136 + u * 8));
                bb[2 * jp][0] = t[0]; bb[2 * jp][1] = t[1];
                bb[2 * jp + 1][0] = t[2]; bb[2 * jp + 1][1] = t[3];
            }
#pragma unroll
            for (int im = 0; im < 4; im++)
#pragma unroll
                for (int jn = 0; jn < 8; jn++) {
                    mma_f16(acc[im][jn], ah[im], bb[jn]);
                    mma_f16(acc[im][jn], al[im], bb[jn]);
                }
        }
        CP_WAIT(1);
        __syncthreads();
    }

    const int gid = lane >> 2, tig = lane & 3;
#pragma unroll
    for (int im = 0; im < 4; im++) {
        int row = bm * 128 + wm * 64 + im * 16 + gid;
#pragma unroll
        for (int jn = 0; jn < 8; jn++) {
            int col = bn * 128 + wn * 64 + jn * 8 + tig * 2;
            *(float2*)&C[(size_t)row * ldc + col] = make_float2(acc[im][jn][0], acc[im][jn][1]);
            *(float2*)&C[(size_t)(row + 8) * ldc + col] = make_float2(acc[im][jn][2], acc[im][jn][3]);
        }
    }
}

// ---------------------------------------------------------------------------
// RoPE + split from fused qkv fp32. One warp per (s, head).
// Heads 0..31: q (scaled by SCALE, hi+lo out). Heads 32..39: k (hi out).
// ---------------------------------------------------------------------------
__global__ void rope_split_kernel(const float* __restrict__ qkvf,
                                  const float* __restrict__ cosb, const float* __restrict__ sinb,
                                  __half* __restrict__ qh, __half* __restrict__ ql,
                                  __half* __restrict__ kh)
{
    int gw = blockIdx.x * 8 + (threadIdx.x >> 5);
    int lane = threadIdx.x & 31;
    int s = gw / 40, hh = gw % 40;
    if (s >= SEQ) return;

    float c0 = cosb[(size_t)s * 64 + lane];
    float s0 = sinb[(size_t)s * 64 + lane];
    float c1 = cosb[(size_t)s * 64 + 32 + lane];
    float s1 = sinb[(size_t)s * 64 + 32 + lane];

    if (hh < NH) {
        const float* src = qkvf + (size_t)s * 6144 + hh * 128;
        float x0 = src[lane], x1 = src[32 + lane], x2 = src[64 + lane], x3 = src[96 + lane];
        float v[4];
        v[0] = (x0 * c0 - x1 * s0) * SCALE;
        v[1] = (x1 * c1 + x0 * s1) * SCALE;
        v[2] = x2 * SCALE;
        v[3] = x3 * SCALE;
        size_t base = (size_t)s * 4096 + hh * 128;
        const int off[4] = {0, 32, 64, 96};
#pragma unroll
        for (int i = 0; i < 4; i++) {
            __half h = __float2half_rn(v[i]);
            qh[base + off[i] + lane] = h;
            ql[base + off[i] + lane] = __float2half_rn(v[i] - __half2float(h));
        }
    } else {
        const float* src = qkvf + (size_t)s * 6144 + 4096 + (hh - NH) * 128;
        float x0 = src[lane], x1 = src[32 + lane], x2 = src[64 + lane], x3 = src[96 + lane];
        size_t base = (size_t)s * 1024 + (hh - NH) * 128;
        kh[base + lane]      = __float2half_rn(x0 * c0 - x1 * s0);
        kh[base + 32 + lane] = __float2half_rn(x1 * c1 + x0 * s1);
        kh[base + 64 + lane] = __float2half_rn(x2);
        kh[base + 96 + lane] = __float2half_rn(x3);
    }
}

// ---------------------------------------------------------------------------
// Flash attention. CTA: 128 q-rows (8 warps x 16 rows), key tiles of 64,
// double-buffered K/Vh/Vl. Q pre-scaled hi+lo in smem. Causal + sink.
// Writes attn hi+lo fp16.
// smem halves: Qh 128*136, Ql 128*136, K 2*64*136, Vh 2*64*136, Vl 2*64*136
// ---------------------------------------------------------------------------
#define FSMEM ((2 * 128 * 136 + 6 * 64 * 136) * 2)

__global__ __launch_bounds__(256, 1)
void flash_kernel(const __half* __restrict__ qh, const __half* __restrict__ ql,
                  const __half* __restrict__ kh,
                  const __half* __restrict__ vh, const __half* __restrict__ vl,
                  const float* __restrict__ sinks,
                  __half* __restrict__ ath, __half* __restrict__ atl)
{
    extern __shared__ __half sm[];
    __half* Qh = sm;
    __half* Ql = Qh + 128 * 136;
    __half* Ks = Ql + 128 * 136;
    __half* Vs = Ks + 2 * 64 * 136;
    __half* Vx = Vs + 2 * 64 * 136;

    const int qt = gridDim.x - 1 - blockIdx.x;
    const int h = blockIdx.y, kvh = h >> 2;
    const int tid = threadIdx.x, lane = tid & 31, w = tid >> 5;
    const int gid = lane >> 2, tig = lane & 3;

    {   // Q tiles (hi, lo)
        const __half* src = qh + (size_t)(qt * 128) * 4096 + h * 128;
        const __half* srl = ql + (size_t)(qt * 128) * 4096 + h * 128;
#pragma unroll
        for (int i = 0; i < 8; i++) {
            int id = tid + i * 256;
            int r = id >> 4, u = id & 15;
            cp16(smem_u32(Qh + r * 136 + u * 8), src + (size_t)r * 4096 + u * 8);
            cp16(smem_u32(Ql + r * 136 + u * 8), srl + (size_t)r * 4096 + u * 8);
        }
    }
    auto loadKV = [&](int kt) {
        int buf = (kt & 1) * 64 * 136;
        const __half* ks = kh + (size_t)(kt * 64) * 1024 + kvh * 128;
        const __half* vs = vh + (size_t)(kt * 64) * 1024 + kvh * 128;
        const __half* vx = vl + (size_t)(kt * 64) * 1024 + kvh * 128;
#pragma unroll
        for (int i = 0; i < 4; i++) {
            int id = tid + i * 256;
            int r = id >> 4, u = id & 15;
            cp16(smem_u32(Ks + buf + r * 136 + u * 8), ks + (size_t)r * 1024 + u * 8);
            cp16(smem_u32(Vs + buf + r * 136 + u * 8), vs + (size_t)r * 1024 + u * 8);
            cp16(smem_u32(Vx + buf + r * 136 + u * 8), vx + (size_t)r * 1024 + u * 8);
        }
    };

    loadKV(0);
    CP_COMMIT();

    float m0 = -1e30f, m1 = -1e30f, l0 = 0.f, l1 = 0.f;
    float O[16][4];
#pragma unroll
    for (int i = 0; i < 16; i++)
#pragma unroll
        for (int j = 0; j < 4; j++) O[i][j] = 0.f;

    const int nkt = 2 * (qt + 1);
    const int rowg0 = qt * 128 + w * 16 + gid;

    for (int kt = 0; kt < nkt; kt++) {
        CP_WAIT(0);
        __syncthreads();
        if (kt + 1 < nkt) loadKV(kt + 1);
        CP_COMMIT();

        const __half* Kb  = Ks + (kt & 1) * 64 * 136;
        const __half* Vbh = Vs + (kt & 1) * 64 * 136;
        const __half* Vbl = Vx + (kt & 1) * 64 * 136;

        // ---- S = Q K^T (Q x2) ----
        float S[8][4];
#pragma unroll
        for (int i = 0; i < 8; i++)
#pragma unroll
            for (int j = 0; j < 4; j++) S[i][j] = 0.f;
#pragma unroll
        for (int kk = 0; kk < 8; kk++) {
            uint32_t qa[4], qb[4], kb[8][2];
            {
                int r = w * 16 + (lane & 15);
                int u = kk * 2 + (lane >> 4);
                ldsm4(qa, smem_u32(Qh + r * 136 + u * 8));
                ldsm4(qb, smem_u32(Ql + r * 136 + u * 8));
            }
#pragma unroll
            for (int jp = 0; jp < 4; jp++) {
                int r = jp * 16 + (lane & 15);
                int u = kk * 2 + (lane >> 4);
                uint32_t t[4];
                ldsm4(t, smem_u32(Kb + r * 136 + u * 8));
                kb[2 * jp][0] = t[0]; kb[2 * jp][1] = t[2];
                kb[2 * jp + 1][0] = t[1]; kb[2 * jp + 1][1] = t[3];
            }
#pragma unroll
            for (int jn = 0; jn < 8; jn++) {
                mma_f16(S[jn], qa, kb[jn]);
                mma_f16(S[jn], qb, kb[jn]);
            }
        }

        // ---- causal mask ----
        if (kt * 64 + 63 > qt * 128 + w * 16) {
#pragma unroll
            for (int jn = 0; jn < 8; jn++) {
                int colb = kt * 64 + jn * 8 + tig * 2;
                if (colb > rowg0)         S[jn][0] = -1e30f;
                if (colb + 1 > rowg0)     S[jn][1] = -1e30f;
                if (colb > rowg0 + 8)     S[jn][2] = -1e30f;
                if (colb + 1 > rowg0 + 8) S[jn][3] = -1e30f;
            }
        }

        // ---- online softmax ----
        float mr0 = -1e30f, mr1 = -1e30f;
#pragma unroll
        for (int jn = 0; jn < 8; jn++) {
            mr0 = fmaxf(mr0, fmaxf(S[jn][0], S[jn][1]));
            mr1 = fmaxf(mr1, fmaxf(S[jn][2], S[jn][3]));
        }
        mr0 = fmaxf(mr0, __shfl_xor_sync(0xffffffff, mr0, 1));
        mr0 = fmaxf(mr0, __shfl_xor_sync(0xffffffff, mr0, 2));
        mr1 = fmaxf(mr1, __shfl_xor_sync(0xffffffff, mr1, 1));
        mr1 = fmaxf(mr1, __shfl_xor_sync(0xffffffff, mr1, 2));
        float mn0 = fmaxf(m0, mr0), mn1 = fmaxf(m1, mr1);
        float a0 = __expf(m0 - mn0), a1 = __expf(m1 - mn1);

        float sum0 = 0.f, sum1 = 0.f;
        uint32_t ph[4][4], pl[4][4];
#pragma unroll
        for (int j = 0; j < 4; j++) {
#pragma unroll
            for (int t = 0; t < 2; t++) {
                float p0 = __expf(S[2 * j + t][0] - mn0);
                float p1 = __expf(S[2 * j + t][1] - mn0);
                float p2 = __expf(S[2 * j + t][2] - mn1);
                float p3 = __expf(S[2 * j + t][3] - mn1);
                sum0 += p0 + p1;
                sum1 += p2 + p3;
                __half h0 = __float2half_rn(p0), h1 = __float2half_rn(p1);
                __half h2 = __float2half_rn(p2), h3 = __float2half_rn(p3);
                __half2 u01; u01.x = h0; u01.y = h1;
                __half2 u23; u23.x = h2; u23.y = h3;
                ph[j][2 * t + 0] = *(uint32_t*)&u01;
                ph[j][2 * t + 1] = *(uint32_t*)&u23;
                pl[j][2 * t + 0] = pack_h2(p0 - __half2float(h0), p1 - __half2float(h1));
                pl[j][2 * t + 1] = pack_h2(p2 - __half2float(h2), p3 - __half2float(h3));
            }
        }
        sum0 += __shfl_xor_sync(0xffffffff, sum0, 1);
        sum0 += __shfl_xor_sync(0xffffffff, sum0, 2);
        sum1 += __shfl_xor_sync(0xffffffff, sum1, 1);
        sum1 += __shfl_xor_sync(0xffffffff, sum1, 2);
        l0 = l0 * a0 + sum0;
        l1 = l1 * a1 + sum1;
        m0 = mn0; m1 = mn1;
#pragma unroll
        for (int nt = 0; nt < 16; nt++) {
            O[nt][0] *= a0; O[nt][1] *= a0;
            O[nt][2] *= a1; O[nt][3] *= a1;
        }

        // ---- O += P V (P x2, V x2: PhVh + PlVh + PhVl) ----
#pragma unroll
        for (int ks = 0; ks < 4; ks++) {
            uint32_t vb[16][2];
#pragma unroll
            for (int jp = 0; jp < 8; jp++) {
                int r = ks * 16 + (lane & 15);
                int u = jp * 2 + (lane >> 4);
                uint32_t t[4];
                ldsm4t(t, smem_u32(Vbh + r * 136 + u * 8));
                vb[2 * jp][0] = t[0]; vb[2 * jp][1] = t[1];
                vb[2 * jp + 1][0] = t[2]; vb[2 * jp + 1][1] = t[3];
            }
#pragma unroll
            for (int nt = 0; nt < 16; nt++) {
                mma_f16(O[nt], ph[ks], vb[nt]);
                mma_f16(O[nt], pl[ks], vb[nt]);
            }
#pragma unroll
            for (int jp = 0; jp < 8; jp++) {
                int r = ks * 16 + (lane & 15);
                int u = jp * 2 + (lane >> 4);
                uint32_t t[4];
                ldsm4t(t, smem_u32(Vbl + r * 136 + u * 8));
                vb[2 * jp][0] = t[0]; vb[2 * jp][1] = t[1];
                vb[2 * jp + 1][0] = t[2]; vb[2 * jp + 1][1] = t[3];
            }
#pragma unroll
            for (int nt = 0; nt < 16; nt++) {
                mma_f16(O[nt], ph[ks], vb[nt]);
            }
        }
    }

    // ---- sink + normalize + store hi/lo ----
    float sink = sinks[h];
    l0 += __expf(sink - m0);
    l1 += __expf(sink - m1);
    float i0 = 1.f / l0, i1 = 1.f / l1;
    int row0 = qt * 128 + w * 16 + gid;
#pragma unroll
    for (int nt = 0; nt < 16; nt++) {
        int col = h * 128 + nt * 8 + tig * 2;
        float f0 = O[nt][0] * i0, f1 = O[nt][1] * i0;
        float f2 = O[nt][2] * i1, f3 = O[nt][3] * i1;
        __half h0 = __float2half_rn(f0), h1 = __float2half_rn(f1);
        __half h2 = __float2half_rn(f2), h3 = __float2half_rn(f3);
        __half2 u01; u01.x = h0; u01.y = h1;
        __half2 u23; u23.x = h2; u23.y = h3;
        *(__half2*)&ath[(size_t)row0 * 4096 + col] = u01;
        *(__half2*)&ath[(size_t)(row0 + 8) * 4096 + col] = u23;
        *(uint32_t*)&atl[(size_t)row0 * 4096 + col] =
            pack_h2(f0 - __half2float(h0), f1 - __half2float(h1));
        *(uint32_t*)&atl[(size_t)(row0 + 8) * 4096 + col] =
            pack_h2(f2 - __half2float(h2), f3 - __half2float(h3));
    }
}

// ---------------------------------------------------------------------------
extern "C" void kernel_launch(void* const* d_in, const int* in_sizes, int n_in,
                              void* d_out, int out_size)
{
    const float* X_in  = (const float*)d_in[0];
    const float* cosb  = (const float*)d_in[1];
    const float* sinb  = (const float*)d_in[2];
    const float* Wq_in = (const float*)d_in[4];
    const float* Wk_in = (const float*)d_in[5];
    const float* Wv_in = (const float*)d_in[6];
    const float* Wo_in = (const float*)d_in[7];
    const float* sinks = (const float*)d_in[8];
    float* out = (float*)d_out;

    __half *Xh, *Xl, *Wqkv, *Woh, *qh, *ql, *kh, *vh, *vl, *ath, *atl;
    float *qkvf;
    cudaGetSymbolAddress((void**)&Xh,   g_Xh);
    cudaGetSymbolAddress((void**)&Xl,   g_Xl);
    cudaGetSymbolAddress((void**)&Wqkv, g_Wqkv);
    cudaGetSymbolAddress((void**)&Woh,  g_Woh);
    cudaGetSymbolAddress((void**)&qkvf, g_qkvf);
    cudaGetSymbolAddress((void**)&qh,   g_qh);
    cudaGetSymbolAddress((void**)&ql,   g_ql);
    cudaGetSymbolAddress((void**)&kh,   g_kh);
    cudaGetSymbolAddress((void**)&vh,   g_vh);
    cudaGetSymbolAddress((void**)&vl,   g_vl);
    cudaGetSymbolAddress((void**)&ath,  g_ath);
    cudaGetSymbolAddress((void**)&atl,  g_atl);

    cudaFuncSetAttribute((const void*)hgemm, cudaFuncAttributeMaxDynamicSharedMemorySize, PSMEM);
    cudaFuncSetAttribute((const void*)flash_kernel, cudaFuncAttributeMaxDynamicSharedMemorySize, FSMEM);

    // 0. splits
    split2_kernel<<<2048, 256>>>(X_in, Xh, Xl, SEQ * HID);
    split1s_kernel<<<4096, 256>>>(Wq_in, Wqkv, HID, 4096, 6144, 0);
    split1s_kernel<<<1024, 256>>>(Wk_in, Wqkv, HID, 1024, 6144, 4096);
    split1s_kernel<<<1024, 256>>>(Wv_in, Wqkv, HID, 1024, 6144, 5120);
    split1s_kernel<<<4096, 256>>>(Wo_in, Woh, 4096, HID, HID, 0);

    // 1. fused QKV projection: qkvf[2048][6144] = (Xh+Xl) @ Wqkv
    hgemm<<<dim3(48, 16), 128, PSMEM>>>(Xh, Xl, Wqkv, qkvf,
                                        SEQ, 6144, HID, HID, 6144, 6144);

    // 2. RoPE + splits (q scaled), v split
    rope_split_kernel<<<SEQ * 40 / 8, 256>>>(qkvf, cosb, sinb, qh, ql, kh);
    vsplit_kernel<<<1024, 256>>>(qkvf, vh, vl);

    // 3. flash attention (causal + sink), attn hi/lo out
    flash_kernel<<<dim3(16, 32), 256, FSMEM>>>(qh, ql, kh, vh, vl, sinks, ath, atl);

    // 4. output projection: out = (ath+atl) @ Woh
    hgemm<<<dim3(32, 16), 128, PSMEM>>>(ath, atl, Woh, out,
                                        SEQ, HID, 4096, 4096, HID, HID);
}